// round 1
// baseline (speedup 1.0000x reference)
#include <cuda_runtime.h>
#include <cstddef>

#define NNODES 4096
#define NB 4
#define BN (NNODES * NB)
#define DFEAT 240
#define KNN 8
#define PRE_STRIDE 448   // 432 floats used, padded for alignment

// Scratch (allocation-free rule: __device__ globals)
__device__ int   g_knn[BN * KNN];
__device__ float g_pre[(size_t)BN * PRE_STRIDE];

// T[a][k] = (Cm[a] . ev)[k], Cm = real Wigner 1x1->2 coupling / sqrt(5)
__device__ __forceinline__ void compute_T(float ex, float ey, float ez, float T[5][3]) {
    const float sc = 0.31622776601683794f;   // 1/sqrt(2)/sqrt(5)
    const float tc = 0.18257418583505536f;   // 1/sqrt(6)/sqrt(5)
    T[0][0] = sc * ey;  T[0][1] = sc * ex;   T[0][2] = 0.f;
    T[1][0] = sc * ez;  T[1][1] = 0.f;       T[1][2] = sc * ex;
    T[2][0] = 0.f;      T[2][1] = sc * ez;   T[2][2] = sc * ey;
    T[3][0] = sc * ex;  T[3][1] = -sc * ey;  T[3][2] = 0.f;
    T[4][0] = -tc * ex; T[4][1] = -tc * ey;  T[4][2] = 2.f * tc * ez;
}

// ============================================================================
// Kernel 1: brute-force kNN per batch. Warp per query, lane scans 128
// candidates keeping a sorted top-8 in registers, then warp merge.
// ============================================================================
__global__ __launch_bounds__(256) void knn_kernel(const float* __restrict__ coords) {
    __shared__ float sx[NNODES], sy[NNODES], sz[NNODES];
    int b = blockIdx.y;
    const float* cb = coords + (size_t)b * NNODES * 3;
    for (int k = threadIdx.x; k < NNODES; k += 256) {
        sx[k] = cb[3 * k];
        sy[k] = cb[3 * k + 1];
        sz[k] = cb[3 * k + 2];
    }
    __syncthreads();

    int warp = threadIdx.x >> 5, lane = threadIdx.x & 31;
    int q = (blockIdx.x << 3) + warp;
    float qx = sx[q], qy = sy[q], qz = sz[q];

    float bd[8];
    int   bi[8];
#pragma unroll
    for (int p = 0; p < 8; p++) { bd[p] = 3.9e38f; bi[p] = 0x7fffffff; }

#pragma unroll 4
    for (int t = 0; t < NNODES / 32; t++) {
        int j = lane + (t << 5);
        float dx = sx[j] - qx, dy = sy[j] - qy, dz = sz[j] - qz;
        float d2 = fmaf(dx, dx, fmaf(dy, dy, dz * dz));
        if (j == q) d2 = 3.8e38f;                 // exclude self (ref adds 1e9)
        if (d2 < bd[7]) {                          // strict <: keeps earlier index on tie
            bd[7] = d2; bi[7] = j;
#pragma unroll
            for (int p = 7; p >= 1; --p) {
                if (bd[p] < bd[p - 1]) {
                    float tv = bd[p]; bd[p] = bd[p - 1]; bd[p - 1] = tv;
                    int   ti = bi[p]; bi[p] = bi[p - 1]; bi[p - 1] = ti;
                }
            }
        }
    }
    __syncthreads();  // done with sx/sy as coords; reuse for merge

    float* md = sx;
    int*   mi = (int*)sy;
    int base = (warp << 8) + (lane << 3);
#pragma unroll
    for (int p = 0; p < 8; p++) { md[base + p] = bd[p]; mi[base + p] = bi[p]; }
    __syncwarp();

    int cur = 0;
    int qflat = b * NNODES + q;
    for (int r = 0; r < KNN; r++) {
        float v  = md[base + cur];
        int   id = mi[base + cur];
        float bv = v; int bid = id;
#pragma unroll
        for (int off = 16; off >= 1; off >>= 1) {
            float ov  = __shfl_xor_sync(0xffffffffu, bv, off);
            int   oid = __shfl_xor_sync(0xffffffffu, bid, off);
            if (ov < bv || (ov == bv && oid < bid)) { bv = ov; bid = oid; }
        }
        if (id == bid) cur++;   // candidate indices are unique -> exactly one lane advances
        if (lane == 0) g_knn[qflat * KNN + r] = b * NNODES + bid;  // flat sender id
    }
}

// ============================================================================
// Kernel 2: per-node precompute of W-contracted features (hoisted out of edges)
//   p1[w]   = c1 * sum_u x0[u]   W1[u,w]        (32)
//   q[w,i]  = c2 * sum_u x1[u,i] W2[u,w]        (64x3)
//   s[w,a]  = c4 * sum_u x2[u,a] W4[u,w]        (32x5)
//   r[w,i]  = c3 * sum_u x1[u,i] W3[u,w]        (16x3)
// Layout per node: [0:32) p1 | [32:224) q as [i][w] | [224:384) s as [a][w] | [384:432) r as [i][w]
// ============================================================================
__global__ __launch_bounds__(256) void pre_kernel(
    const float* __restrict__ feats,
    const float* __restrict__ W1, const float* __restrict__ W2,
    const float* __restrict__ W3, const float* __restrict__ W4) {
    __shared__ float sW1[64 * 32], sW2[32 * 64], sW3[32 * 16], sW4[16 * 32];
    __shared__ float sx[8][DFEAT];
    for (int k = threadIdx.x; k < 2048; k += 256) { sW1[k] = W1[k]; sW2[k] = W2[k]; }
    for (int k = threadIdx.x; k < 512;  k += 256) { sW3[k] = W3[k]; sW4[k] = W4[k]; }

    int warp = threadIdx.x >> 5, lane = threadIdx.x & 31;
    int node = (blockIdx.x << 3) + warp;
    const float* xf = feats + (size_t)node * DFEAT;
    for (int k = lane; k < DFEAT; k += 32) sx[warp][k] = xf[k];
    __syncthreads();

    const float* xw = sx[warp];
    float* P = g_pre + (size_t)node * PRE_STRIDE;
    const float c1 = 0.11180339887498949f;   // sqrt(1/80)
    const float c2 = 0.10206207261596575f;   // sqrt(1/96)
    const float c3 = 0.39528470752104744f;   // sqrt(5/32)
    const float c4 = 0.19364916731037085f;   // sqrt(3/80)

    {   // p1
        float acc = 0.f;
#pragma unroll
        for (int u = 0; u < 64; u++) acc = fmaf(xw[u], sW1[u * 32 + lane], acc);
        P[lane] = c1 * acc;
    }
#pragma unroll
    for (int i = 0; i < 3; i++) {   // q (lane handles w = 2*lane, 2*lane+1)
        float a0 = 0.f, a1 = 0.f;
#pragma unroll
        for (int u = 0; u < 32; u++) {
            float xv = xw[64 + u * 3 + i];
            a0 = fmaf(xv, sW2[u * 64 + 2 * lane],     a0);
            a1 = fmaf(xv, sW2[u * 64 + 2 * lane + 1], a1);
        }
        P[32 + i * 64 + 2 * lane]     = c2 * a0;
        P[32 + i * 64 + 2 * lane + 1] = c2 * a1;
    }
#pragma unroll
    for (int a = 0; a < 5; a++) {   // s
        float acc = 0.f;
#pragma unroll
        for (int u = 0; u < 16; u++) acc = fmaf(xw[160 + u * 5 + a], sW4[u * 32 + lane], acc);
        P[224 + a * 32 + lane] = c4 * acc;
    }
    if (lane < 16) {                // r
#pragma unroll
        for (int i = 0; i < 3; i++) {
            float acc = 0.f;
#pragma unroll
            for (int u = 0; u < 32; u++) acc = fmaf(xw[64 + u * 3 + i], sW3[u * 16 + lane], acc);
            P[384 + i * 16 + lane] = c3 * acc;
        }
    }
}

// ============================================================================
// Kernel 3: warp-per-node aggregation over 8 neighbors + output linears.
// Lane w accumulates: m0[2w],m0[2w+1] | agg1[w][0..2] | (w<16) agg2[w][0..4]
// ============================================================================
__global__ __launch_bounds__(256) void agg_kernel(
    const float* __restrict__ coords,
    const float* __restrict__ L0, const float* __restrict__ L1,
    const float* __restrict__ L2, float* __restrict__ out) {
    __shared__ float sL0[4096], sL1[1024], sL2[256];
    __shared__ float sagg[8][DFEAT];
    for (int k = threadIdx.x; k < 4096; k += 256) sL0[k] = L0[k];
    for (int k = threadIdx.x; k < 1024; k += 256) sL1[k] = L1[k];
    if (threadIdx.x < 256) sL2[threadIdx.x] = L2[threadIdx.x];

    int warp = threadIdx.x >> 5, lane = threadIdx.x & 31;
    int node = (blockIdx.x << 3) + warp;
    float qx = coords[node * 3], qy = coords[node * 3 + 1], qz = coords[node * 3 + 2];

    float a0_0 = 0.f, a0_1 = 0.f;
    float a1[3] = {0.f, 0.f, 0.f};
    float a2[5] = {0.f, 0.f, 0.f, 0.f, 0.f};
    __syncthreads();

#pragma unroll
    for (int r = 0; r < KNN; r++) {
        int snd = g_knn[node * KNN + r];
        float ex = coords[snd * 3]     - qx;
        float ey = coords[snd * 3 + 1] - qy;
        float ez = coords[snd * 3 + 2] - qz;
        float T[5][3];
        compute_T(ex, ey, ez, T);
        const float* P = g_pre + (size_t)snd * PRE_STRIDE;

        float p = P[lane];                                  // p1 ⊗ ev -> m1
        a1[0] = fmaf(p, ex, a1[0]);
        a1[1] = fmaf(p, ey, a1[1]);
        a1[2] = fmaf(p, ez, a1[2]);
#pragma unroll
        for (int a = 0; a < 5; a++) {                       // s . T -> m1
            float sv = P[224 + a * 32 + lane];
            a1[0] = fmaf(sv, T[a][0], a1[0]);
            a1[1] = fmaf(sv, T[a][1], a1[1]);
            a1[2] = fmaf(sv, T[a][2], a1[2]);
        }
        {                                                   // q . ev -> m0
            float e[3] = {ex, ey, ez};
#pragma unroll
            for (int i = 0; i < 3; i++) {
                a0_0 = fmaf(P[32 + i * 64 + 2 * lane],     e[i], a0_0);
                a0_1 = fmaf(P[32 + i * 64 + 2 * lane + 1], e[i], a0_1);
            }
        }
        if (lane < 16) {                                    // r . S (= T^t) -> m2
#pragma unroll
            for (int i = 0; i < 3; i++) {
                float rv = P[384 + i * 16 + lane];
#pragma unroll
                for (int k = 0; k < 5; k++) a2[k] = fmaf(rv, T[k][i], a2[k]);
            }
        }
    }

    float* ag = sagg[warp];
    ag[2 * lane]     = a0_0;
    ag[2 * lane + 1] = a0_1;
    ag[64 + lane * 3 + 0] = a1[0];
    ag[64 + lane * 3 + 1] = a1[1];
    ag[64 + lane * 3 + 2] = a1[2];
    if (lane < 16) {
#pragma unroll
        for (int k = 0; k < 5; k++) ag[160 + lane * 5 + k] = a2[k];
    }
    __syncwarp();

    float* o = out + (size_t)node * DFEAT;
    {   // y0 = agg0 @ L0 / 8
        float y0 = 0.f, y1v = 0.f;
#pragma unroll
        for (int u = 0; u < 64; u++) {
            float av = ag[u];
            y0  = fmaf(av, sL0[u * 64 + 2 * lane],     y0);
            y1v = fmaf(av, sL0[u * 64 + 2 * lane + 1], y1v);
        }
        o[2 * lane]     = 0.125f * y0;
        o[2 * lane + 1] = 0.125f * y1v;
    }
    {   // y1[w,k] = sum_u agg1[u,k] L1[u,w] / sqrt(32)
        float y[3] = {0.f, 0.f, 0.f};
#pragma unroll
        for (int u = 0; u < 32; u++) {
            float lw = sL1[u * 32 + lane];
            y[0] = fmaf(ag[64 + u * 3 + 0], lw, y[0]);
            y[1] = fmaf(ag[64 + u * 3 + 1], lw, y[1]);
            y[2] = fmaf(ag[64 + u * 3 + 2], lw, y[2]);
        }
        const float l1s = 0.17677669529663687f;  // 1/sqrt(32)
        o[64 + lane * 3 + 0] = l1s * y[0];
        o[64 + lane * 3 + 1] = l1s * y[1];
        o[64 + lane * 3 + 2] = l1s * y[2];
    }
    if (lane < 16) {   // y2[w,k] = sum_u agg2[u,k] L2[u,w] / 4
        float y[5] = {0.f, 0.f, 0.f, 0.f, 0.f};
#pragma unroll
        for (int u = 0; u < 16; u++) {
            float lw = sL2[u * 16 + lane];
#pragma unroll
            for (int k = 0; k < 5; k++) y[k] = fmaf(ag[160 + u * 5 + k], lw, y[k]);
        }
#pragma unroll
        for (int k = 0; k < 5; k++) o[160 + lane * 5 + k] = 0.25f * y[k];
    }
}

// ============================================================================
extern "C" void kernel_launch(void* const* d_in, const int* in_sizes, int n_in,
                              void* d_out, int out_size) {
    const float* feats  = (const float*)d_in[0];  // (4,4096,240)
    const float* coords = (const float*)d_in[1];  // (4,4096,3)
    const float* W1 = (const float*)d_in[2];      // (64,32)
    const float* W2 = (const float*)d_in[3];      // (32,64)
    const float* W3 = (const float*)d_in[4];      // (32,16)
    const float* W4 = (const float*)d_in[5];      // (16,32)
    const float* L0 = (const float*)d_in[6];      // (64,64)
    const float* L1 = (const float*)d_in[7];      // (32,32)
    const float* L2 = (const float*)d_in[8];      // (16,16)
    float* out = (float*)d_out;

    knn_kernel<<<dim3(NNODES / 8, NB), 256>>>(coords);
    pre_kernel<<<BN / 8, 256>>>(feats, W1, W2, W3, W4);
    agg_kernel<<<BN / 8, 256>>>(coords, L0, L1, L2, out);
}

// round 2
// speedup vs baseline: 1.0281x; 1.0281x over previous
#include <cuda_runtime.h>
#include <cstddef>

#define NNODES 4096
#define NB 4
#define BN (NNODES * NB)
#define DFEAT 240
#define KNN 8
#define PRE_STRIDE 448   // 432 floats used, padded for alignment
#define KNN_TS 2048      // candidate tile size (24KB shared)

// Scratch (allocation-free rule: __device__ globals)
__device__ int   g_knn[BN * KNN];
__device__ float g_pre[(size_t)BN * PRE_STRIDE];

// T[a][k] = (Cm[a] . ev)[k], Cm = real Wigner 1x1->2 coupling / sqrt(5)
__device__ __forceinline__ void compute_T(float ex, float ey, float ez, float T[5][3]) {
    const float sc = 0.31622776601683794f;   // 1/sqrt(2)/sqrt(5)
    const float tc = 0.18257418583505536f;   // 1/sqrt(6)/sqrt(5)
    T[0][0] = sc * ey;  T[0][1] = sc * ex;   T[0][2] = 0.f;
    T[1][0] = sc * ez;  T[1][1] = 0.f;       T[1][2] = sc * ex;
    T[2][0] = 0.f;      T[2][1] = sc * ez;   T[2][2] = sc * ey;
    T[3][0] = sc * ex;  T[3][1] = -sc * ey;  T[3][2] = 0.f;
    T[4][0] = -tc * ex; T[4][1] = -tc * ey;  T[4][2] = 2.f * tc * ez;
}

// ============================================================================
// Kernel 1: brute-force kNN, THREAD-per-query.
// Block = 64 threads = 64 queries; candidates stream through shared tiles.
// Private sorted top-8 in registers; insert path is rare (~24% of warp-iters).
// ============================================================================
__global__ __launch_bounds__(64) void knn_kernel(const float* __restrict__ coords) {
    __shared__ float sc3[KNN_TS * 3];            // AoS tile (LDS broadcast in hot loop)
    int b = blockIdx.y;
    const float* cb = coords + (size_t)b * NNODES * 3;

    int q = (blockIdx.x << 6) + threadIdx.x;     // query node within batch
    float qx = cb[3 * q], qy = cb[3 * q + 1], qz = cb[3 * q + 2];

    float bd[8];
    int   bi[8];
#pragma unroll
    for (int p = 0; p < 8; p++) { bd[p] = 3.9e38f; bi[p] = 0x7fffffff; }

    for (int tile = 0; tile < NNODES; tile += KNN_TS) {
        __syncthreads();
        // coalesced linear copy of the tile (2048 cands * 12B)
        for (int k = threadIdx.x; k < KNN_TS * 3; k += 64)
            sc3[k] = cb[tile * 3 + k];
        __syncthreads();

        float worst = bd[7];
#pragma unroll 4
        for (int j = 0; j < KNN_TS; j++) {
            float dx = sc3[3 * j]     - qx;
            float dy = sc3[3 * j + 1] - qy;
            float dz = sc3[3 * j + 2] - qz;
            float d2 = fmaf(dx, dx, fmaf(dy, dy, dz * dz));
            if (d2 < worst) {                       // rare path
                int gj = tile + j;
                if (gj != q) {                      // exclude self here (off hot path)
                    bd[7] = d2; bi[7] = gj;
#pragma unroll
                    for (int p = 7; p >= 1; --p) {
                        if (bd[p] < bd[p - 1]) {
                            float tv = bd[p]; bd[p] = bd[p - 1]; bd[p - 1] = tv;
                            int   ti = bi[p]; bi[p] = bi[p - 1]; bi[p - 1] = ti;
                        }
                    }
                    worst = bd[7];
                }
            }
        }
    }

    int qflat = b * NNODES + q;
#pragma unroll
    for (int r = 0; r < KNN; r++)
        g_knn[qflat * KNN + r] = b * NNODES + bi[r];
}

// ============================================================================
// Kernel 2: per-node precompute of W-contracted features (hoisted out of edges)
//   p1[w]   = c1 * sum_u x0[u]   W1[u,w]        (32)
//   q[w,i]  = c2 * sum_u x1[u,i] W2[u,w]        (64x3)
//   s[w,a]  = c4 * sum_u x2[u,a] W4[u,w]        (32x5)
//   r[w,i]  = c3 * sum_u x1[u,i] W3[u,w]        (16x3)
// Layout per node: [0:32) p1 | [32:224) q as [i][w] | [224:384) s as [a][w] | [384:432) r as [i][w]
// ============================================================================
__global__ __launch_bounds__(256) void pre_kernel(
    const float* __restrict__ feats,
    const float* __restrict__ W1, const float* __restrict__ W2,
    const float* __restrict__ W3, const float* __restrict__ W4) {
    __shared__ float sW1[64 * 32], sW2[32 * 64], sW3[32 * 16], sW4[16 * 32];
    __shared__ float sx[8][DFEAT];
    for (int k = threadIdx.x; k < 2048; k += 256) { sW1[k] = W1[k]; sW2[k] = W2[k]; }
    for (int k = threadIdx.x; k < 512;  k += 256) { sW3[k] = W3[k]; sW4[k] = W4[k]; }

    int warp = threadIdx.x >> 5, lane = threadIdx.x & 31;
    int node = (blockIdx.x << 3) + warp;
    const float* xf = feats + (size_t)node * DFEAT;
    for (int k = lane; k < DFEAT; k += 32) sx[warp][k] = xf[k];
    __syncthreads();

    const float* xw = sx[warp];
    float* P = g_pre + (size_t)node * PRE_STRIDE;
    const float c1 = 0.11180339887498949f;   // sqrt(1/80)
    const float c2 = 0.10206207261596575f;   // sqrt(1/96)
    const float c3 = 0.39528470752104744f;   // sqrt(5/32)
    const float c4 = 0.19364916731037085f;   // sqrt(3/80)

    {   // p1
        float acc = 0.f;
#pragma unroll
        for (int u = 0; u < 64; u++) acc = fmaf(xw[u], sW1[u * 32 + lane], acc);
        P[lane] = c1 * acc;
    }
#pragma unroll
    for (int i = 0; i < 3; i++) {   // q (lane handles w = 2*lane, 2*lane+1)
        float a0 = 0.f, a1 = 0.f;
#pragma unroll
        for (int u = 0; u < 32; u++) {
            float xv = xw[64 + u * 3 + i];
            a0 = fmaf(xv, sW2[u * 64 + 2 * lane],     a0);
            a1 = fmaf(xv, sW2[u * 64 + 2 * lane + 1], a1);
        }
        P[32 + i * 64 + 2 * lane]     = c2 * a0;
        P[32 + i * 64 + 2 * lane + 1] = c2 * a1;
    }
#pragma unroll
    for (int a = 0; a < 5; a++) {   // s
        float acc = 0.f;
#pragma unroll
        for (int u = 0; u < 16; u++) acc = fmaf(xw[160 + u * 5 + a], sW4[u * 32 + lane], acc);
        P[224 + a * 32 + lane] = c4 * acc;
    }
    if (lane < 16) {                // r
#pragma unroll
        for (int i = 0; i < 3; i++) {
            float acc = 0.f;
#pragma unroll
            for (int u = 0; u < 32; u++) acc = fmaf(xw[64 + u * 3 + i], sW3[u * 16 + lane], acc);
            P[384 + i * 16 + lane] = c3 * acc;
        }
    }
}

// ============================================================================
// Kernel 3: warp-per-node aggregation over 8 neighbors + output linears.
// Lane w accumulates: m0[2w],m0[2w+1] | agg1[w][0..2] | (w<16) agg2[w][0..4]
// ============================================================================
__global__ __launch_bounds__(256) void agg_kernel(
    const float* __restrict__ coords,
    const float* __restrict__ L0, const float* __restrict__ L1,
    const float* __restrict__ L2, float* __restrict__ out) {
    __shared__ float sL0[4096], sL1[1024], sL2[256];
    __shared__ float sagg[8][DFEAT];
    for (int k = threadIdx.x; k < 4096; k += 256) sL0[k] = L0[k];
    for (int k = threadIdx.x; k < 1024; k += 256) sL1[k] = L1[k];
    if (threadIdx.x < 256) sL2[threadIdx.x] = L2[threadIdx.x];

    int warp = threadIdx.x >> 5, lane = threadIdx.x & 31;
    int node = (blockIdx.x << 3) + warp;
    float qx = coords[node * 3], qy = coords[node * 3 + 1], qz = coords[node * 3 + 2];

    float a0_0 = 0.f, a0_1 = 0.f;
    float a1[3] = {0.f, 0.f, 0.f};
    float a2[5] = {0.f, 0.f, 0.f, 0.f, 0.f};
    __syncthreads();

#pragma unroll
    for (int r = 0; r < KNN; r++) {
        int snd = g_knn[node * KNN + r];
        float ex = coords[snd * 3]     - qx;
        float ey = coords[snd * 3 + 1] - qy;
        float ez = coords[snd * 3 + 2] - qz;
        float T[5][3];
        compute_T(ex, ey, ez, T);
        const float* P = g_pre + (size_t)snd * PRE_STRIDE;

        float p = P[lane];                                  // p1 ⊗ ev -> m1
        a1[0] = fmaf(p, ex, a1[0]);
        a1[1] = fmaf(p, ey, a1[1]);
        a1[2] = fmaf(p, ez, a1[2]);
#pragma unroll
        for (int a = 0; a < 5; a++) {                       // s . T -> m1
            float sv = P[224 + a * 32 + lane];
            a1[0] = fmaf(sv, T[a][0], a1[0]);
            a1[1] = fmaf(sv, T[a][1], a1[1]);
            a1[2] = fmaf(sv, T[a][2], a1[2]);
        }
        {                                                   // q . ev -> m0
            float e[3] = {ex, ey, ez};
#pragma unroll
            for (int i = 0; i < 3; i++) {
                a0_0 = fmaf(P[32 + i * 64 + 2 * lane],     e[i], a0_0);
                a0_1 = fmaf(P[32 + i * 64 + 2 * lane + 1], e[i], a0_1);
            }
        }
        if (lane < 16) {                                    // r . S (= T^t) -> m2
#pragma unroll
            for (int i = 0; i < 3; i++) {
                float rv = P[384 + i * 16 + lane];
#pragma unroll
                for (int k = 0; k < 5; k++) a2[k] = fmaf(rv, T[k][i], a2[k]);
            }
        }
    }

    float* ag = sagg[warp];
    ag[2 * lane]     = a0_0;
    ag[2 * lane + 1] = a0_1;
    ag[64 + lane * 3 + 0] = a1[0];
    ag[64 + lane * 3 + 1] = a1[1];
    ag[64 + lane * 3 + 2] = a1[2];
    if (lane < 16) {
#pragma unroll
        for (int k = 0; k < 5; k++) ag[160 + lane * 5 + k] = a2[k];
    }
    __syncwarp();

    float* o = out + (size_t)node * DFEAT;
    {   // y0 = agg0 @ L0 / 8
        float y0 = 0.f, y1v = 0.f;
#pragma unroll
        for (int u = 0; u < 64; u++) {
            float av = ag[u];
            y0  = fmaf(av, sL0[u * 64 + 2 * lane],     y0);
            y1v = fmaf(av, sL0[u * 64 + 2 * lane + 1], y1v);
        }
        o[2 * lane]     = 0.125f * y0;
        o[2 * lane + 1] = 0.125f * y1v;
    }
    {   // y1[w,k] = sum_u agg1[u,k] L1[u,w] / sqrt(32)
        float y[3] = {0.f, 0.f, 0.f};
#pragma unroll
        for (int u = 0; u < 32; u++) {
            float lw = sL1[u * 32 + lane];
            y[0] = fmaf(ag[64 + u * 3 + 0], lw, y[0]);
            y[1] = fmaf(ag[64 + u * 3 + 1], lw, y[1]);
            y[2] = fmaf(ag[64 + u * 3 + 2], lw, y[2]);
        }
        const float l1s = 0.17677669529663687f;  // 1/sqrt(32)
        o[64 + lane * 3 + 0] = l1s * y[0];
        o[64 + lane * 3 + 1] = l1s * y[1];
        o[64 + lane * 3 + 2] = l1s * y[2];
    }
    if (lane < 16) {   // y2[w,k] = sum_u agg2[u,k] L2[u,w] / 4
        float y[5] = {0.f, 0.f, 0.f, 0.f, 0.f};
#pragma unroll
        for (int u = 0; u < 16; u++) {
            float lw = sL2[u * 16 + lane];
#pragma unroll
            for (int k = 0; k < 5; k++) y[k] = fmaf(ag[160 + u * 5 + k], lw, y[k]);
        }
#pragma unroll
        for (int k = 0; k < 5; k++) o[160 + lane * 5 + k] = 0.25f * y[k];
    }
}

// ============================================================================
extern "C" void kernel_launch(void* const* d_in, const int* in_sizes, int n_in,
                              void* d_out, int out_size) {
    const float* feats  = (const float*)d_in[0];  // (4,4096,240)
    const float* coords = (const float*)d_in[1];  // (4,4096,3)
    const float* W1 = (const float*)d_in[2];      // (64,32)
    const float* W2 = (const float*)d_in[3];      // (32,64)
    const float* W3 = (const float*)d_in[4];      // (32,16)
    const float* W4 = (const float*)d_in[5];      // (16,32)
    const float* L0 = (const float*)d_in[6];      // (64,64)
    const float* L1 = (const float*)d_in[7];      // (32,32)
    const float* L2 = (const float*)d_in[8];      // (16,16)
    float* out = (float*)d_out;

    knn_kernel<<<dim3(NNODES / 64, NB), 64>>>(coords);
    pre_kernel<<<BN / 8, 256>>>(feats, W1, W2, W3, W4);
    agg_kernel<<<BN / 8, 256>>>(coords, L0, L1, L2, out);
}

// round 3
// speedup vs baseline: 1.3981x; 1.3599x over previous
#include <cuda_runtime.h>
#include <cstddef>

#define NNODES 4096
#define NB 4
#define BN (NNODES * NB)
#define DFEAT 240
#define KNN 8
#define PRE_STRIDE 448   // 432 floats used, padded for alignment
#define NCHUNK 4
#define CHUNK (NNODES / NCHUNK)   // 1024 candidates per chunk

// Scratch (allocation-free rule: __device__ globals)
__device__ int   g_knn[BN * KNN];
__device__ float g_pre[(size_t)BN * PRE_STRIDE];
__device__ float g_pd[BN * NCHUNK * KNN];
__device__ int   g_pi[BN * NCHUNK * KNN];

// T[a][k] = (Cm[a] . ev)[k], Cm = real Wigner 1x1->2 coupling / sqrt(5)
__device__ __forceinline__ void compute_T(float ex, float ey, float ez, float T[5][3]) {
    const float sc = 0.31622776601683794f;   // 1/sqrt(2)/sqrt(5)
    const float tc = 0.18257418583505536f;   // 1/sqrt(6)/sqrt(5)
    T[0][0] = sc * ey;  T[0][1] = sc * ex;   T[0][2] = 0.f;
    T[1][0] = sc * ez;  T[1][1] = 0.f;       T[1][2] = sc * ex;
    T[2][0] = 0.f;      T[2][1] = sc * ez;   T[2][2] = sc * ey;
    T[3][0] = sc * ex;  T[3][1] = -sc * ey;  T[3][2] = 0.f;
    T[4][0] = -tc * ex; T[4][1] = -tc * ey;  T[4][2] = 2.f * tc * ez;
}

// ============================================================================
// Kernel 1a: partial kNN. Thread = (query, chunk); scans 1024 candidates from
// a shared SoA tile with float4 broadcasts (4 cands/trip), keeps sorted top-8.
// ============================================================================
__global__ __launch_bounds__(128) void knn_part_kernel(const float* __restrict__ coords) {
    __shared__ float sx[CHUNK], sy[CHUNK], sz[CHUNK];
    int b = blockIdx.y;
    int chunk = blockIdx.z;
    int cbase = chunk * CHUNK;
    const float* cb = coords + (size_t)b * NNODES * 3;

    for (int k = threadIdx.x; k < CHUNK; k += 128) {
        sx[k] = cb[(cbase + k) * 3];
        sy[k] = cb[(cbase + k) * 3 + 1];
        sz[k] = cb[(cbase + k) * 3 + 2];
    }
    __syncthreads();

    int q = (blockIdx.x << 7) + threadIdx.x;
    float qx = cb[3 * q], qy = cb[3 * q + 1], qz = cb[3 * q + 2];

    float bd[8];
    int   bi[8];
#pragma unroll
    for (int p = 0; p < 8; p++) { bd[p] = 3.9e38f; bi[p] = 0x7fffffff; }
    float worst = 3.9e38f;

    const float4* px = (const float4*)sx;
    const float4* py = (const float4*)sy;
    const float4* pz = (const float4*)sz;

#pragma unroll 2
    for (int g = 0; g < CHUNK / 4; g++) {
        float4 X = px[g], Y = py[g], Z = pz[g];
        float dx0 = X.x - qx, dy0 = Y.x - qy, dz0 = Z.x - qz;
        float dx1 = X.y - qx, dy1 = Y.y - qy, dz1 = Z.y - qz;
        float dx2 = X.z - qx, dy2 = Y.z - qy, dz2 = Z.z - qz;
        float dx3 = X.w - qx, dy3 = Y.w - qy, dz3 = Z.w - qz;
        float d0 = fmaf(dx0, dx0, fmaf(dy0, dy0, dz0 * dz0));
        float d1 = fmaf(dx1, dx1, fmaf(dy1, dy1, dz1 * dz1));
        float d2 = fmaf(dx2, dx2, fmaf(dy2, dy2, dz2 * dz2));
        float d3 = fmaf(dx3, dx3, fmaf(dy3, dy3, dz3 * dz3));
        float m = fminf(fminf(d0, d1), fminf(d2, d3));
        if (m < worst) {                          // rare after warm-up
            int j0 = cbase + (g << 2);
            float dv[4] = {d0, d1, d2, d3};
#pragma unroll
            for (int k = 0; k < 4; k++) {
                float dk = dv[k];
                int gj = j0 + k;
                if (dk < bd[7] && gj != q) {      // strict <: earliest index on tie
                    bd[7] = dk; bi[7] = gj;
#pragma unroll
                    for (int p = 7; p >= 1; --p) {
                        if (bd[p] < bd[p - 1]) {
                            float tv = bd[p]; bd[p] = bd[p - 1]; bd[p - 1] = tv;
                            int   ti = bi[p]; bi[p] = bi[p - 1]; bi[p - 1] = ti;
                        }
                    }
                }
            }
            worst = bd[7];
        }
    }

    int qflat = b * NNODES + q;
    int obase = (qflat * NCHUNK + chunk) * KNN;
#pragma unroll
    for (int r = 0; r < KNN; r++) {
        g_pd[obase + r] = bd[r];
        g_pi[obase + r] = b * NNODES + bi[r];     // flat sender id
    }
}

// ============================================================================
// Kernel 1b: merge NCHUNK sorted top-8 lists -> global top-8 per query.
// ============================================================================
__global__ __launch_bounds__(256) void knn_merge_kernel() {
    int qf = blockIdx.x * 256 + threadIdx.x;
    int base = qf * NCHUNK * KNN;

    float hv[NCHUNK];
    int   hi[NCHUNK];
    int   p[NCHUNK];
#pragma unroll
    for (int c = 0; c < NCHUNK; c++) {
        hv[c] = g_pd[base + c * KNN];
        hi[c] = g_pi[base + c * KNN];
        p[c] = 1;
    }
#pragma unroll
    for (int r = 0; r < KNN; r++) {
        int bc = 0;
        float bv = hv[0]; int bid = hi[0];
#pragma unroll
        for (int c = 1; c < NCHUNK; c++) {
            if (hv[c] < bv || (hv[c] == bv && hi[c] < bid)) { bv = hv[c]; bid = hi[c]; bc = c; }
        }
        g_knn[qf * KNN + r] = bid;
#pragma unroll
        for (int c = 0; c < NCHUNK; c++) {
            if (c == bc) {
                if (p[c] < KNN) {
                    hv[c] = g_pd[base + c * KNN + p[c]];
                    hi[c] = g_pi[base + c * KNN + p[c]];
                    p[c]++;
                } else {
                    hv[c] = 3.95e38f;
                }
            }
        }
    }
}

// ============================================================================
// Kernel 2: per-node precompute of W-contracted features (hoisted out of edges)
// Layout per node: [0:32) p1 | [32:224) q as [i][w] | [224:384) s as [a][w] | [384:432) r as [i][w]
// ============================================================================
__global__ __launch_bounds__(256) void pre_kernel(
    const float* __restrict__ feats,
    const float* __restrict__ W1, const float* __restrict__ W2,
    const float* __restrict__ W3, const float* __restrict__ W4) {
    __shared__ float sW1[64 * 32], sW2[32 * 64], sW3[32 * 16], sW4[16 * 32];
    __shared__ float sx[8][DFEAT];
    for (int k = threadIdx.x; k < 2048; k += 256) { sW1[k] = W1[k]; sW2[k] = W2[k]; }
    for (int k = threadIdx.x; k < 512;  k += 256) { sW3[k] = W3[k]; sW4[k] = W4[k]; }

    int warp = threadIdx.x >> 5, lane = threadIdx.x & 31;
    int node = (blockIdx.x << 3) + warp;
    const float* xf = feats + (size_t)node * DFEAT;
    for (int k = lane; k < DFEAT; k += 32) sx[warp][k] = xf[k];
    __syncthreads();

    const float* xw = sx[warp];
    float* P = g_pre + (size_t)node * PRE_STRIDE;
    const float c1 = 0.11180339887498949f;   // sqrt(1/80)
    const float c2 = 0.10206207261596575f;   // sqrt(1/96)
    const float c3 = 0.39528470752104744f;   // sqrt(5/32)
    const float c4 = 0.19364916731037085f;   // sqrt(3/80)

    {   // p1
        float acc = 0.f;
#pragma unroll
        for (int u = 0; u < 64; u++) acc = fmaf(xw[u], sW1[u * 32 + lane], acc);
        P[lane] = c1 * acc;
    }
#pragma unroll
    for (int i = 0; i < 3; i++) {   // q (lane handles w = 2*lane, 2*lane+1)
        float a0 = 0.f, a1 = 0.f;
#pragma unroll
        for (int u = 0; u < 32; u++) {
            float xv = xw[64 + u * 3 + i];
            a0 = fmaf(xv, sW2[u * 64 + 2 * lane],     a0);
            a1 = fmaf(xv, sW2[u * 64 + 2 * lane + 1], a1);
        }
        P[32 + i * 64 + 2 * lane]     = c2 * a0;
        P[32 + i * 64 + 2 * lane + 1] = c2 * a1;
    }
#pragma unroll
    for (int a = 0; a < 5; a++) {   // s
        float acc = 0.f;
#pragma unroll
        for (int u = 0; u < 16; u++) acc = fmaf(xw[160 + u * 5 + a], sW4[u * 32 + lane], acc);
        P[224 + a * 32 + lane] = c4 * acc;
    }
    if (lane < 16) {                // r
#pragma unroll
        for (int i = 0; i < 3; i++) {
            float acc = 0.f;
#pragma unroll
            for (int u = 0; u < 32; u++) acc = fmaf(xw[64 + u * 3 + i], sW3[u * 16 + lane], acc);
            P[384 + i * 16 + lane] = c3 * acc;
        }
    }
}

// ============================================================================
// Kernel 3: warp-per-node aggregation over 8 neighbors + output linears.
// ============================================================================
__global__ __launch_bounds__(256) void agg_kernel(
    const float* __restrict__ coords,
    const float* __restrict__ L0, const float* __restrict__ L1,
    const float* __restrict__ L2, float* __restrict__ out) {
    __shared__ float sL0[4096], sL1[1024], sL2[256];
    __shared__ float sagg[8][DFEAT];
    for (int k = threadIdx.x; k < 4096; k += 256) sL0[k] = L0[k];
    for (int k = threadIdx.x; k < 1024; k += 256) sL1[k] = L1[k];
    if (threadIdx.x < 256) sL2[threadIdx.x] = L2[threadIdx.x];

    int warp = threadIdx.x >> 5, lane = threadIdx.x & 31;
    int node = (blockIdx.x << 3) + warp;
    float qx = coords[node * 3], qy = coords[node * 3 + 1], qz = coords[node * 3 + 2];

    float a0_0 = 0.f, a0_1 = 0.f;
    float a1[3] = {0.f, 0.f, 0.f};
    float a2[5] = {0.f, 0.f, 0.f, 0.f, 0.f};
    __syncthreads();

#pragma unroll
    for (int r = 0; r < KNN; r++) {
        int snd = g_knn[node * KNN + r];
        float ex = coords[snd * 3]     - qx;
        float ey = coords[snd * 3 + 1] - qy;
        float ez = coords[snd * 3 + 2] - qz;
        float T[5][3];
        compute_T(ex, ey, ez, T);
        const float* P = g_pre + (size_t)snd * PRE_STRIDE;

        float p = P[lane];                                  // p1 ⊗ ev -> m1
        a1[0] = fmaf(p, ex, a1[0]);
        a1[1] = fmaf(p, ey, a1[1]);
        a1[2] = fmaf(p, ez, a1[2]);
#pragma unroll
        for (int a = 0; a < 5; a++) {                       // s . T -> m1
            float sv = P[224 + a * 32 + lane];
            a1[0] = fmaf(sv, T[a][0], a1[0]);
            a1[1] = fmaf(sv, T[a][1], a1[1]);
            a1[2] = fmaf(sv, T[a][2], a1[2]);
        }
        {                                                   // q . ev -> m0
            float e[3] = {ex, ey, ez};
#pragma unroll
            for (int i = 0; i < 3; i++) {
                a0_0 = fmaf(P[32 + i * 64 + 2 * lane],     e[i], a0_0);
                a0_1 = fmaf(P[32 + i * 64 + 2 * lane + 1], e[i], a0_1);
            }
        }
        if (lane < 16) {                                    // r . S (= T^t) -> m2
#pragma unroll
            for (int i = 0; i < 3; i++) {
                float rv = P[384 + i * 16 + lane];
#pragma unroll
                for (int k = 0; k < 5; k++) a2[k] = fmaf(rv, T[k][i], a2[k]);
            }
        }
    }

    float* ag = sagg[warp];
    ag[2 * lane]     = a0_0;
    ag[2 * lane + 1] = a0_1;
    ag[64 + lane * 3 + 0] = a1[0];
    ag[64 + lane * 3 + 1] = a1[1];
    ag[64 + lane * 3 + 2] = a1[2];
    if (lane < 16) {
#pragma unroll
        for (int k = 0; k < 5; k++) ag[160 + lane * 5 + k] = a2[k];
    }
    __syncwarp();

    float* o = out + (size_t)node * DFEAT;
    {   // y0 = agg0 @ L0 / 8
        float y0 = 0.f, y1v = 0.f;
#pragma unroll
        for (int u = 0; u < 64; u++) {
            float av = ag[u];
            y0  = fmaf(av, sL0[u * 64 + 2 * lane],     y0);
            y1v = fmaf(av, sL0[u * 64 + 2 * lane + 1], y1v);
        }
        o[2 * lane]     = 0.125f * y0;
        o[2 * lane + 1] = 0.125f * y1v;
    }
    {   // y1[w,k] = sum_u agg1[u,k] L1[u,w] / sqrt(32)
        float y[3] = {0.f, 0.f, 0.f};
#pragma unroll
        for (int u = 0; u < 32; u++) {
            float lw = sL1[u * 32 + lane];
            y[0] = fmaf(ag[64 + u * 3 + 0], lw, y[0]);
            y[1] = fmaf(ag[64 + u * 3 + 1], lw, y[1]);
            y[2] = fmaf(ag[64 + u * 3 + 2], lw, y[2]);
        }
        const float l1s = 0.17677669529663687f;  // 1/sqrt(32)
        o[64 + lane * 3 + 0] = l1s * y[0];
        o[64 + lane * 3 + 1] = l1s * y[1];
        o[64 + lane * 3 + 2] = l1s * y[2];
    }
    if (lane < 16) {   // y2[w,k] = sum_u agg2[u,k] L2[u,w] / 4
        float y[5] = {0.f, 0.f, 0.f, 0.f, 0.f};
#pragma unroll
        for (int u = 0; u < 16; u++) {
            float lw = sL2[u * 16 + lane];
#pragma unroll
            for (int k = 0; k < 5; k++) y[k] = fmaf(ag[160 + u * 5 + k], lw, y[k]);
        }
#pragma unroll
        for (int k = 0; k < 5; k++) o[160 + lane * 5 + k] = 0.25f * y[k];
    }
}

// ============================================================================
extern "C" void kernel_launch(void* const* d_in, const int* in_sizes, int n_in,
                              void* d_out, int out_size) {
    const float* feats  = (const float*)d_in[0];  // (4,4096,240)
    const float* coords = (const float*)d_in[1];  // (4,4096,3)
    const float* W1 = (const float*)d_in[2];      // (64,32)
    const float* W2 = (const float*)d_in[3];      // (32,64)
    const float* W3 = (const float*)d_in[4];      // (32,16)
    const float* W4 = (const float*)d_in[5];      // (16,32)
    const float* L0 = (const float*)d_in[6];      // (64,64)
    const float* L1 = (const float*)d_in[7];      // (32,32)
    const float* L2 = (const float*)d_in[8];      // (16,16)
    float* out = (float*)d_out;

    knn_part_kernel<<<dim3(NNODES / 128, NB, NCHUNK), 128>>>(coords);
    knn_merge_kernel<<<BN / 256, 256>>>();
    pre_kernel<<<BN / 8, 256>>>(feats, W1, W2, W3, W4);
    agg_kernel<<<BN / 8, 256>>>(coords, L0, L1, L2, out);
}

// round 4
// speedup vs baseline: 1.4261x; 1.0200x over previous
#include <cuda_runtime.h>
#include <cstddef>

#define NNODES 4096
#define NB 4
#define BN (NNODES * NB)
#define DFEAT 240
#define KNN 8
#define NCHUNK 8
#define CHUNK (NNODES / NCHUNK)   // 512 candidates per chunk

// Scratch (allocation-free rule: __device__ globals)
__device__ int   g_knn[BN * KNN];
__device__ float g_pd[BN * NCHUNK * KNN];
__device__ int   g_pi[BN * NCHUNK * KNN];
// Fused (W @ L) matrices, output scales baked in
__device__ float g_WL0[32 * 64];   // (W2@L0)  * c2/8
__device__ float g_WL1a[64 * 32];  // (W1@L1)  * c1/sqrt(32)
__device__ float g_WL1b[16 * 32];  // (W4@L1)  * c4/sqrt(32)
__device__ float g_WL2[32 * 16];   // (W3@L2)  * c3/4

// T[a][k] = (Cm[a] . ev)[k], Cm = real Wigner 1x1->2 coupling / sqrt(5)
__device__ __forceinline__ void compute_T(float ex, float ey, float ez, float T[5][3]) {
    const float sc = 0.31622776601683794f;   // 1/sqrt(2)/sqrt(5)
    const float tc = 0.18257418583505536f;   // 1/sqrt(6)/sqrt(5)
    T[0][0] = sc * ey;  T[0][1] = sc * ex;   T[0][2] = 0.f;
    T[1][0] = sc * ez;  T[1][1] = 0.f;       T[1][2] = sc * ex;
    T[2][0] = 0.f;      T[2][1] = sc * ez;   T[2][2] = sc * ey;
    T[3][0] = sc * ex;  T[3][1] = -sc * ey;  T[3][2] = 0.f;
    T[4][0] = -tc * ex; T[4][1] = -tc * ey;  T[4][2] = 2.f * tc * ez;
}

// ============================================================================
// Kernel 1a: partial kNN. Thread = (query, chunk). Rank by s = |c|^2/2 - q.c
// (monotone in d^2). Tile holds float4 (x,y,z,h): 1 LDS.128 + 3 FMA/candidate.
// Unsorted top-8 with tracked worst slot; sorted once at the end.
// ============================================================================
__global__ __launch_bounds__(128) void knn_part_kernel(const float* __restrict__ coords) {
    __shared__ float4 tile[CHUNK];                // 8KB
    int b = blockIdx.y, chunk = blockIdx.z;
    int cbase = chunk * CHUNK;
    const float* cb = coords + (size_t)b * NNODES * 3;

    for (int k = threadIdx.x; k < CHUNK; k += 128) {
        float x = cb[(cbase + k) * 3];
        float y = cb[(cbase + k) * 3 + 1];
        float z = cb[(cbase + k) * 3 + 2];
        tile[k] = make_float4(x, y, z, 0.5f * fmaf(x, x, fmaf(y, y, z * z)));
    }
    __syncthreads();

    int q = (blockIdx.x << 7) + threadIdx.x;
    float qx = cb[3 * q], qy = cb[3 * q + 1], qz = cb[3 * q + 2];
    float nqx = -qx, nqy = -qy, nqz = -qz;

    float bd[8];
    int   bi[8];
#pragma unroll
    for (int p = 0; p < 8; p++) { bd[p] = 3.9e38f; bi[p] = 0x7fffffff; }
    float worst = 3.9e38f;
    int   wslot = 0;

#pragma unroll 2
    for (int g = 0; g < CHUNK / 4; g++) {
        float4 c0 = tile[4 * g],     c1 = tile[4 * g + 1];
        float4 c2 = tile[4 * g + 2], c3 = tile[4 * g + 3];
        float s0 = fmaf(nqx, c0.x, fmaf(nqy, c0.y, fmaf(nqz, c0.z, c0.w)));
        float s1 = fmaf(nqx, c1.x, fmaf(nqy, c1.y, fmaf(nqz, c1.z, c1.w)));
        float s2 = fmaf(nqx, c2.x, fmaf(nqy, c2.y, fmaf(nqz, c2.z, c2.w)));
        float s3 = fmaf(nqx, c3.x, fmaf(nqy, c3.y, fmaf(nqz, c3.z, c3.w)));
        float m = fminf(fminf(s0, s1), fminf(s2, s3));
        if (m < worst) {                          // rare after warm-up
            int j0 = cbase + (g << 2);
            float sv[4] = {s0, s1, s2, s3};
#pragma unroll
            for (int k = 0; k < 4; k++) {
                int gj = j0 + k;
                if (sv[k] < worst && gj != q) {   // strict <: earliest index wins ties
                    bd[wslot] = sv[k]; bi[wslot] = gj;
                    // recompute worst slot
                    worst = bd[0]; wslot = 0;
#pragma unroll
                    for (int p = 1; p < 8; p++)
                        if (bd[p] > worst) { worst = bd[p]; wslot = p; }
                }
            }
        }
    }

    // sort the 8 survivors by (value, index) ascending
#pragma unroll
    for (int p = 1; p < 8; p++) {
#pragma unroll
        for (int t = 7; t >= 1; t--) {
            if (t <= p) {
                bool sw = (bd[t] < bd[t - 1]) || (bd[t] == bd[t - 1] && bi[t] < bi[t - 1]);
                if (sw) {
                    float tv = bd[t]; bd[t] = bd[t - 1]; bd[t - 1] = tv;
                    int   ti = bi[t]; bi[t] = bi[t - 1]; bi[t - 1] = ti;
                }
            }
        }
    }

    int qflat = b * NNODES + q;
    int obase = (qflat * NCHUNK + chunk) * KNN;
#pragma unroll
    for (int r = 0; r < KNN; r++) {
        g_pd[obase + r] = bd[r];
        g_pi[obase + r] = b * NNODES + bi[r];     // flat sender id
    }
}

// ============================================================================
// Kernel 1b: merge NCHUNK sorted top-8 lists -> global top-8 per query.
// ============================================================================
__global__ __launch_bounds__(256) void knn_merge_kernel() {
    int qf = blockIdx.x * 256 + threadIdx.x;
    int base = qf * NCHUNK * KNN;

    float hv[NCHUNK];
    int   hi[NCHUNK];
    int   p[NCHUNK];
#pragma unroll
    for (int c = 0; c < NCHUNK; c++) {
        hv[c] = g_pd[base + c * KNN];
        hi[c] = g_pi[base + c * KNN];
        p[c] = 1;
    }
#pragma unroll
    for (int r = 0; r < KNN; r++) {
        int bc = 0;
        float bv = hv[0]; int bid = hi[0];
#pragma unroll
        for (int c = 1; c < NCHUNK; c++) {
            if (hv[c] < bv || (hv[c] == bv && hi[c] < bid)) { bv = hv[c]; bid = hi[c]; bc = c; }
        }
        g_knn[qf * KNN + r] = bid;
#pragma unroll
        for (int c = 0; c < NCHUNK; c++) {
            if (c == bc) {
                if (p[c] < KNN) {
                    hv[c] = g_pd[base + c * KNN + p[c]];
                    hi[c] = g_pi[base + c * KNN + p[c]];
                    p[c]++;
                } else {
                    hv[c] = 3.95e38f;
                }
            }
        }
    }
}

// ============================================================================
// Kernel 2: fuse W and L matrices (W commutes with aggregation) + bake scales.
// 5120 outputs, one per thread. grid = 20 x 256.
// ============================================================================
__global__ __launch_bounds__(256) void fuse_kernel(
    const float* __restrict__ W1, const float* __restrict__ W2,
    const float* __restrict__ W3, const float* __restrict__ W4,
    const float* __restrict__ L0, const float* __restrict__ L1,
    const float* __restrict__ L2) {
    const float c1 = 0.11180339887498949f;   // sqrt(1/80)
    const float c2 = 0.10206207261596575f;   // sqrt(1/96)
    const float c3 = 0.39528470752104744f;   // sqrt(5/32)
    const float c4 = 0.19364916731037085f;   // sqrt(3/80)
    const float is32 = 0.17677669529663687f; // 1/sqrt(32)
    int idx = blockIdx.x * 256 + threadIdx.x;
    if (idx < 2048) {                         // WL0 = W2@L0 : (32,64)
        int u = idx >> 6, w2 = idx & 63;
        float acc = 0.f;
        for (int w = 0; w < 64; w++) acc = fmaf(W2[u * 64 + w], L0[w * 64 + w2], acc);
        g_WL0[idx] = (c2 * 0.125f) * acc;
    } else if (idx < 4096) {                  // WL1a = W1@L1 : (64,32)
        int t = idx - 2048, u = t >> 5, w2 = t & 31;
        float acc = 0.f;
        for (int w = 0; w < 32; w++) acc = fmaf(W1[u * 32 + w], L1[w * 32 + w2], acc);
        g_WL1a[t] = (c1 * is32) * acc;
    } else if (idx < 4608) {                  // WL1b = W4@L1 : (16,32)
        int t = idx - 4096, u = t >> 5, w2 = t & 31;
        float acc = 0.f;
        for (int w = 0; w < 32; w++) acc = fmaf(W4[u * 32 + w], L1[w * 32 + w2], acc);
        g_WL1b[t] = (c4 * is32) * acc;
    } else {                                  // WL2 = W3@L2 : (32,16)
        int t = idx - 4608, u = t >> 4, w2 = t & 15;
        float acc = 0.f;
        for (int w = 0; w < 16; w++) acc = fmaf(W3[u * 16 + w], L2[w * 16 + w2], acc);
        g_WL2[t] = (c3 * 0.25f) * acc;
    }
}

// ============================================================================
// Kernel 3: fused aggregation. Warp per node: accumulate raw geometry over 8
// neighbors (reading raw features), then apply fused WL matrices.
// Accumulators (per lane u):
//   a0        : sum_e x1[u,i] ev[i]              (u = lane, 32)
//   a1a0/a1a1 : sum_e x0[u] ev[k]                (u = lane, lane+32; k=0..2)
//   a1b[k]    : sum_e sum_a x2[u,a] T[a][k]      (u = lane<16)
//   a2[a]     : sum_e sum_i x1[u,i] T[a][i]      (u = lane, 32)
// ============================================================================
__global__ __launch_bounds__(256) void agg_kernel(
    const float* __restrict__ feats, const float* __restrict__ coords,
    float* __restrict__ out) {
    __shared__ float sWL0[2048], sWL1a[2048], sWL1b[512], sWL2[512];
    __shared__ float sx[8][DFEAT];
    __shared__ float sag[8][440];
    for (int k = threadIdx.x; k < 2048; k += 256) { sWL0[k] = g_WL0[k]; sWL1a[k] = g_WL1a[k]; }
    for (int k = threadIdx.x; k < 512;  k += 256) { sWL1b[k] = g_WL1b[k]; sWL2[k] = g_WL2[k]; }

    int warp = threadIdx.x >> 5, lane = threadIdx.x & 31;
    int node = (blockIdx.x << 3) + warp;
    float qx = coords[node * 3], qy = coords[node * 3 + 1], qz = coords[node * 3 + 2];

    float a0 = 0.f;
    float a1a0[3] = {0.f, 0.f, 0.f};
    float a1a1[3] = {0.f, 0.f, 0.f};
    float a1b[3]  = {0.f, 0.f, 0.f};
    float a2[5]   = {0.f, 0.f, 0.f, 0.f, 0.f};
    __syncthreads();

    float* sxw = sx[warp];
#pragma unroll
    for (int r = 0; r < KNN; r++) {
        int snd = g_knn[node * KNN + r];
        float ex = coords[snd * 3]     - qx;
        float ey = coords[snd * 3 + 1] - qy;
        float ez = coords[snd * 3 + 2] - qz;
        float T[5][3];
        compute_T(ex, ey, ez, T);

        // stage sender features (960B, 16B-aligned)
        const float4* xf4 = (const float4*)(feats + (size_t)snd * DFEAT);
        float4* sx4 = (float4*)sxw;
        sx4[lane] = xf4[lane];
        if (lane < 28) sx4[32 + lane] = xf4[32 + lane];
        __syncwarp();

        float e[3] = {ex, ey, ez};
        // x0 (64) -> a1a
        float f0a = sxw[lane], f0b = sxw[32 + lane];
#pragma unroll
        for (int k = 0; k < 3; k++) {
            a1a0[k] = fmaf(f0a, e[k], a1a0[k]);
            a1a1[k] = fmaf(f0b, e[k], a1a1[k]);
        }
        // x1 (32x3) -> a0, a2
        float x1v[3];
#pragma unroll
        for (int i = 0; i < 3; i++) x1v[i] = sxw[64 + 3 * lane + i];
#pragma unroll
        for (int i = 0; i < 3; i++) a0 = fmaf(x1v[i], e[i], a0);
#pragma unroll
        for (int a = 0; a < 5; a++)
#pragma unroll
            for (int i = 0; i < 3; i++) a2[a] = fmaf(x1v[i], T[a][i], a2[a]);
        // x2 (16x5) -> a1b
        if (lane < 16) {
#pragma unroll
            for (int a = 0; a < 5; a++) {
                float xa = sxw[160 + 5 * lane + a];
#pragma unroll
                for (int k = 0; k < 3; k++) a1b[k] = fmaf(xa, T[a][k], a1b[k]);
            }
        }
        __syncwarp();
    }

    // stage aggregates: [0,32) a0 | 32+3u+k (u<64) a1a | 224+3u+k (u<16) a1b | 272+5u+a a2
    float* ag = sag[warp];
    ag[lane] = a0;
#pragma unroll
    for (int k = 0; k < 3; k++) {
        ag[32 + 3 * lane + k]        = a1a0[k];
        ag[32 + 3 * (lane + 32) + k] = a1a1[k];
    }
    if (lane < 16) {
#pragma unroll
        for (int k = 0; k < 3; k++) ag[224 + 3 * lane + k] = a1b[k];
    }
#pragma unroll
    for (int a = 0; a < 5; a++) ag[272 + 5 * lane + a] = a2[a];
    __syncwarp();

    float* o = out + (size_t)node * DFEAT;
    {   // y0[w'] = sum_u a0[u] WL0[u,w']   (w' = 2lane, 2lane+1)
        float y0 = 0.f, y1v = 0.f;
#pragma unroll
        for (int u = 0; u < 32; u++) {
            float av = ag[u];
            y0  = fmaf(av, sWL0[u * 64 + 2 * lane],     y0);
            y1v = fmaf(av, sWL0[u * 64 + 2 * lane + 1], y1v);
        }
        o[2 * lane]     = y0;
        o[2 * lane + 1] = y1v;
    }
    {   // y1[w',k] = sum_{u<64} a1a[u,k] WL1a[u,w'] + sum_{u<16} a1b[u,k] WL1b[u,w']
        float y[3] = {0.f, 0.f, 0.f};
#pragma unroll
        for (int u = 0; u < 64; u++) {
            float lw = sWL1a[u * 32 + lane];
#pragma unroll
            for (int k = 0; k < 3; k++) y[k] = fmaf(ag[32 + 3 * u + k], lw, y[k]);
        }
#pragma unroll
        for (int u = 0; u < 16; u++) {
            float lw = sWL1b[u * 32 + lane];
#pragma unroll
            for (int k = 0; k < 3; k++) y[k] = fmaf(ag[224 + 3 * u + k], lw, y[k]);
        }
#pragma unroll
        for (int k = 0; k < 3; k++) o[64 + 3 * lane + k] = y[k];
    }
    if (lane < 16) {   // y2[w',a] = sum_u a2[u,a] WL2[u,w']
        float y[5] = {0.f, 0.f, 0.f, 0.f, 0.f};
#pragma unroll
        for (int u = 0; u < 32; u++) {
            float lw = sWL2[u * 16 + lane];
#pragma unroll
            for (int a = 0; a < 5; a++) y[a] = fmaf(ag[272 + 5 * u + a], lw, y[a]);
        }
#pragma unroll
        for (int a = 0; a < 5; a++) o[160 + 5 * lane + a] = y[a];
    }
}

// ============================================================================
extern "C" void kernel_launch(void* const* d_in, const int* in_sizes, int n_in,
                              void* d_out, int out_size) {
    const float* feats  = (const float*)d_in[0];  // (4,4096,240)
    const float* coords = (const float*)d_in[1];  // (4,4096,3)
    const float* W1 = (const float*)d_in[2];      // (64,32)
    const float* W2 = (const float*)d_in[3];      // (32,64)
    const float* W3 = (const float*)d_in[4];      // (32,16)
    const float* W4 = (const float*)d_in[5];      // (16,32)
    const float* L0 = (const float*)d_in[6];      // (64,64)
    const float* L1 = (const float*)d_in[7];      // (32,32)
    const float* L2 = (const float*)d_in[8];      // (16,16)
    float* out = (float*)d_out;

    knn_part_kernel<<<dim3(NNODES / 128, NB, NCHUNK), 128>>>(coords);
    knn_merge_kernel<<<BN / 256, 256>>>();
    fuse_kernel<<<20, 256>>>(W1, W2, W3, W4, L0, L1, L2);
    agg_kernel<<<BN / 8, 256>>>(feats, coords, out);
}

// round 5
// speedup vs baseline: 1.5135x; 1.0613x over previous
#include <cuda_runtime.h>
#include <cstddef>

#define NNODES 4096
#define NB 4
#define BN (NNODES * NB)
#define DFEAT 240
#define KNN 8
#define NCHUNK 8
#define CHUNK (NNODES / NCHUNK)   // 512 candidates per chunk

// Scratch (allocation-free rule: __device__ globals)
__device__ int   g_knn[BN * KNN];
__device__ float g_pd[BN * NCHUNK * KNN];
__device__ int   g_pi[BN * NCHUNK * KNN];
// Fused (W @ L) matrices, output scales baked in
__device__ float g_WL0[32 * 64];   // (W2@L0)  * c2/8
__device__ float g_WL1a[64 * 32];  // (W1@L1)  * c1/sqrt(32)
__device__ float g_WL1b[16 * 32];  // (W4@L1)  * c4/sqrt(32)
__device__ float g_WL2[32 * 16];   // (W3@L2)  * c3/4

// T[a][k] = (Cm[a] . ev)[k], Cm = real Wigner 1x1->2 coupling / sqrt(5)
__device__ __forceinline__ void compute_T(float ex, float ey, float ez, float T[5][3]) {
    const float sc = 0.31622776601683794f;   // 1/sqrt(2)/sqrt(5)
    const float tc = 0.18257418583505536f;   // 1/sqrt(6)/sqrt(5)
    T[0][0] = sc * ey;  T[0][1] = sc * ex;   T[0][2] = 0.f;
    T[1][0] = sc * ez;  T[1][1] = 0.f;       T[1][2] = sc * ex;
    T[2][0] = 0.f;      T[2][1] = sc * ez;   T[2][2] = sc * ey;
    T[3][0] = sc * ex;  T[3][1] = -sc * ey;  T[3][2] = 0.f;
    T[4][0] = -tc * ex; T[4][1] = -tc * ey;  T[4][2] = 2.f * tc * ez;
}

// ============================================================================
// Kernel 1a: partial kNN. Thread = (query, chunk). Rank by s = |c|^2/2 - q.c
// (monotone in d^2). Tile of float4 (x,y,z,h): 1 LDS.128 + 3 FMA / candidate.
// 8 candidates per branch test; sorted top-8 in registers (static indices).
// ============================================================================
__global__ __launch_bounds__(256) void knn_part_kernel(const float* __restrict__ coords) {
    __shared__ float4 tile[CHUNK];                // 8KB
    int b = blockIdx.y, chunk = blockIdx.z;
    int cbase = chunk * CHUNK;
    const float* cb = coords + (size_t)b * NNODES * 3;

    for (int k = threadIdx.x; k < CHUNK; k += 256) {
        float x = cb[(cbase + k) * 3];
        float y = cb[(cbase + k) * 3 + 1];
        float z = cb[(cbase + k) * 3 + 2];
        tile[k] = make_float4(x, y, z, 0.5f * fmaf(x, x, fmaf(y, y, z * z)));
    }
    __syncthreads();

    int q = (blockIdx.x << 8) + threadIdx.x;
    float qx = cb[3 * q], qy = cb[3 * q + 1], qz = cb[3 * q + 2];
    float nqx = -qx, nqy = -qy, nqz = -qz;

    float bd[8];
    int   bi[8];
#pragma unroll
    for (int p = 0; p < 8; p++) { bd[p] = 3.9e38f; bi[p] = 0x7fffffff; }
    float worst = 3.9e38f;

    for (int g = 0; g < CHUNK / 8; g++) {         // 64 iterations
        float sv[8];
#pragma unroll
        for (int k = 0; k < 8; k++) {
            float4 c = tile[8 * g + k];
            sv[k] = fmaf(nqx, c.x, fmaf(nqy, c.y, fmaf(nqz, c.z, c.w)));
        }
        float m01 = fminf(sv[0], sv[1]), m23 = fminf(sv[2], sv[3]);
        float m45 = fminf(sv[4], sv[5]), m67 = fminf(sv[6], sv[7]);
        float m = fminf(fminf(m01, m23), fminf(m45, m67));
        if (m < worst) {                          // rare after warm-up
            int j0 = cbase + (g << 3);
#pragma unroll
            for (int k = 0; k < 8; k++) {
                int gj = j0 + k;
                if (sv[k] < worst && gj != q) {   // strict <: earliest index wins ties
                    bd[7] = sv[k]; bi[7] = gj;
#pragma unroll
                    for (int p = 7; p >= 1; --p) {
                        if (bd[p] < bd[p - 1]) {
                            float tv = bd[p]; bd[p] = bd[p - 1]; bd[p - 1] = tv;
                            int   ti = bi[p]; bi[p] = bi[p - 1]; bi[p - 1] = ti;
                        }
                    }
                    worst = bd[7];
                }
            }
        }
    }

    int qflat = b * NNODES + q;
    int obase = (qflat * NCHUNK + chunk) * KNN;
#pragma unroll
    for (int r = 0; r < KNN; r++) {
        g_pd[obase + r] = bd[r];
        g_pi[obase + r] = b * NNODES + bi[r];     // flat sender id
    }
}

// ============================================================================
// Kernel 1b: merge. Warp per query: 64 candidates in 2 regs/lane, 8 rounds of
// lexicographic (val, idx) butterfly argmin; winner masked out. Set semantics
// suffice (aggregation is a sum over neighbors).
// ============================================================================
__global__ __launch_bounds__(256) void knn_merge_kernel() {
    int warp = threadIdx.x >> 5, lane = threadIdx.x & 31;
    int qf = blockIdx.x * 8 + warp;
    int base = qf * NCHUNK * KNN;                 // 64 contiguous entries

    float v0 = g_pd[base + lane];
    float v1 = g_pd[base + 32 + lane];
    int   i0 = g_pi[base + lane];
    int   i1 = g_pi[base + 32 + lane];

#pragma unroll
    for (int r = 0; r < KNN; r++) {
        float mv; int mi;
        if (v0 < v1 || (v0 == v1 && i0 < i1)) { mv = v0; mi = i0; }
        else                                  { mv = v1; mi = i1; }
#pragma unroll
        for (int off = 16; off >= 1; off >>= 1) {
            float ov = __shfl_xor_sync(0xffffffffu, mv, off);
            int   oi = __shfl_xor_sync(0xffffffffu, mi, off);
            if (ov < mv || (ov == mv && oi < mi)) { mv = ov; mi = oi; }
        }
        if (lane == r) g_knn[qf * KNN + r] = mi;  // any lane; spread stores
        if (i0 == mi) v0 = 3.95e38f;              // node ids unique across chunks
        if (i1 == mi) v1 = 3.95e38f;
    }
}

// ============================================================================
// Kernel 2: fuse W and L matrices (W commutes with aggregation) + bake scales.
// ============================================================================
__global__ __launch_bounds__(256) void fuse_kernel(
    const float* __restrict__ W1, const float* __restrict__ W2,
    const float* __restrict__ W3, const float* __restrict__ W4,
    const float* __restrict__ L0, const float* __restrict__ L1,
    const float* __restrict__ L2) {
    const float c1 = 0.11180339887498949f;   // sqrt(1/80)
    const float c2 = 0.10206207261596575f;   // sqrt(1/96)
    const float c3 = 0.39528470752104744f;   // sqrt(5/32)
    const float c4 = 0.19364916731037085f;   // sqrt(3/80)
    const float is32 = 0.17677669529663687f; // 1/sqrt(32)
    int idx = blockIdx.x * 256 + threadIdx.x;
    if (idx < 2048) {                         // WL0 = W2@L0 : (32,64)
        int u = idx >> 6, w2 = idx & 63;
        float acc = 0.f;
        for (int w = 0; w < 64; w++) acc = fmaf(W2[u * 64 + w], L0[w * 64 + w2], acc);
        g_WL0[idx] = (c2 * 0.125f) * acc;
    } else if (idx < 4096) {                  // WL1a = W1@L1 : (64,32)
        int t = idx - 2048, u = t >> 5, w2 = t & 31;
        float acc = 0.f;
        for (int w = 0; w < 32; w++) acc = fmaf(W1[u * 32 + w], L1[w * 32 + w2], acc);
        g_WL1a[t] = (c1 * is32) * acc;
    } else if (idx < 4608) {                  // WL1b = W4@L1 : (16,32)
        int t = idx - 4096, u = t >> 5, w2 = t & 31;
        float acc = 0.f;
        for (int w = 0; w < 32; w++) acc = fmaf(W4[u * 32 + w], L1[w * 32 + w2], acc);
        g_WL1b[t] = (c4 * is32) * acc;
    } else {                                  // WL2 = W3@L2 : (32,16)
        int t = idx - 4608, u = t >> 4, w2 = t & 15;
        float acc = 0.f;
        for (int w = 0; w < 16; w++) acc = fmaf(W3[u * 16 + w], L2[w * 16 + w2], acc);
        g_WL2[t] = (c3 * 0.25f) * acc;
    }
}

// ============================================================================
// Kernel 3: fused aggregation. Warp per node. Direct LDG of exactly the
// feature elements each lane needs (no smem staging, no per-edge syncs);
// neighbor ids + coords front-batched for MLP. Then fused WL linears.
// ============================================================================
__global__ __launch_bounds__(256) void agg_kernel(
    const float* __restrict__ feats, const float* __restrict__ coords,
    float* __restrict__ out) {
    __shared__ float sWL0[2048], sWL1a[2048], sWL1b[512], sWL2[512];
    __shared__ float sag[8][440];
    for (int k = threadIdx.x; k < 2048; k += 256) { sWL0[k] = g_WL0[k]; sWL1a[k] = g_WL1a[k]; }
    for (int k = threadIdx.x; k < 512;  k += 256) { sWL1b[k] = g_WL1b[k]; sWL2[k] = g_WL2[k]; }

    int warp = threadIdx.x >> 5, lane = threadIdx.x & 31;
    int node = (blockIdx.x << 3) + warp;
    float qx = coords[node * 3], qy = coords[node * 3 + 1], qz = coords[node * 3 + 2];

    // front-batch neighbor ids (32B aligned) and edge vectors
    int4 n0 = *(const int4*)(g_knn + node * KNN);
    int4 n1 = *(const int4*)(g_knn + node * KNN + 4);
    int nbr[8] = {n0.x, n0.y, n0.z, n0.w, n1.x, n1.y, n1.z, n1.w};
    float ex[8], ey[8], ez[8];
#pragma unroll
    for (int r = 0; r < 8; r++) {
        ex[r] = coords[nbr[r] * 3]     - qx;
        ey[r] = coords[nbr[r] * 3 + 1] - qy;
        ez[r] = coords[nbr[r] * 3 + 2] - qz;
    }

    float a0 = 0.f;
    float a1a0[3] = {0.f, 0.f, 0.f};
    float a1a1[3] = {0.f, 0.f, 0.f};
    float a1b[3]  = {0.f, 0.f, 0.f};
    float a2[5]   = {0.f, 0.f, 0.f, 0.f, 0.f};

#pragma unroll
    for (int r = 0; r < KNN; r++) {
        const float* f = feats + (size_t)nbr[r] * DFEAT;
        // issue all feature loads for this edge up front
        float f0a = f[lane];                       // coalesced
        float f0b = f[32 + lane];                  // coalesced
        float x1v[3];
#pragma unroll
        for (int i = 0; i < 3; i++) x1v[i] = f[64 + 3 * lane + i];
        float x2v[5];
        if (lane < 16) {
#pragma unroll
            for (int a = 0; a < 5; a++) x2v[a] = f[160 + 5 * lane + a];
        }

        float T[5][3];
        compute_T(ex[r], ey[r], ez[r], T);
        float e[3] = {ex[r], ey[r], ez[r]};

#pragma unroll
        for (int k = 0; k < 3; k++) {
            a1a0[k] = fmaf(f0a, e[k], a1a0[k]);
            a1a1[k] = fmaf(f0b, e[k], a1a1[k]);
        }
#pragma unroll
        for (int i = 0; i < 3; i++) a0 = fmaf(x1v[i], e[i], a0);
#pragma unroll
        for (int a = 0; a < 5; a++)
#pragma unroll
            for (int i = 0; i < 3; i++) a2[a] = fmaf(x1v[i], T[a][i], a2[a]);
        if (lane < 16) {
#pragma unroll
            for (int a = 0; a < 5; a++)
#pragma unroll
                for (int k = 0; k < 3; k++) a1b[k] = fmaf(x2v[a], T[a][k], a1b[k]);
        }
    }

    __syncthreads();   // sWL ready (placed late: overlaps loads above with other warps)

    // stage aggregates: [0,32) a0 | 32+3u+k (u<64) a1a | 224+3u+k (u<16) a1b | 272+5u+a a2
    float* ag = sag[warp];
    ag[lane] = a0;
#pragma unroll
    for (int k = 0; k < 3; k++) {
        ag[32 + 3 * lane + k]        = a1a0[k];
        ag[32 + 3 * (lane + 32) + k] = a1a1[k];
    }
    if (lane < 16) {
#pragma unroll
        for (int k = 0; k < 3; k++) ag[224 + 3 * lane + k] = a1b[k];
    }
#pragma unroll
    for (int a = 0; a < 5; a++) ag[272 + 5 * lane + a] = a2[a];
    __syncwarp();

    float* o = out + (size_t)node * DFEAT;
    {   // y0[w'] = sum_u a0[u] WL0[u,w']   (w' = 2lane, 2lane+1)
        float y0 = 0.f, y1v = 0.f;
#pragma unroll
        for (int u = 0; u < 32; u++) {
            float av = ag[u];
            y0  = fmaf(av, sWL0[u * 64 + 2 * lane],     y0);
            y1v = fmaf(av, sWL0[u * 64 + 2 * lane + 1], y1v);
        }
        o[2 * lane]     = y0;
        o[2 * lane + 1] = y1v;
    }
    {   // y1[w',k] = sum_{u<64} a1a[u,k] WL1a[u,w'] + sum_{u<16} a1b[u,k] WL1b[u,w']
        float y[3] = {0.f, 0.f, 0.f};
#pragma unroll
        for (int u = 0; u < 64; u++) {
            float lw = sWL1a[u * 32 + lane];
#pragma unroll
            for (int k = 0; k < 3; k++) y[k] = fmaf(ag[32 + 3 * u + k], lw, y[k]);
        }
#pragma unroll
        for (int u = 0; u < 16; u++) {
            float lw = sWL1b[u * 32 + lane];
#pragma unroll
            for (int k = 0; k < 3; k++) y[k] = fmaf(ag[224 + 3 * u + k], lw, y[k]);
        }
#pragma unroll
        for (int k = 0; k < 3; k++) o[64 + 3 * lane + k] = y[k];
    }
    if (lane < 16) {   // y2[w',a] = sum_u a2[u,a] WL2[u,w']
        float y[5] = {0.f, 0.f, 0.f, 0.f, 0.f};
#pragma unroll
        for (int u = 0; u < 32; u++) {
            float lw = sWL2[u * 16 + lane];
#pragma unroll
            for (int a = 0; a < 5; a++) y[a] = fmaf(ag[272 + 5 * u + a], lw, y[a]);
        }
#pragma unroll
        for (int a = 0; a < 5; a++) o[160 + 5 * lane + a] = y[a];
    }
}

// ============================================================================
extern "C" void kernel_launch(void* const* d_in, const int* in_sizes, int n_in,
                              void* d_out, int out_size) {
    const float* feats  = (const float*)d_in[0];  // (4,4096,240)
    const float* coords = (const float*)d_in[1];  // (4,4096,3)
    const float* W1 = (const float*)d_in[2];      // (64,32)
    const float* W2 = (const float*)d_in[3];      // (32,64)
    const float* W3 = (const float*)d_in[4];      // (32,16)
    const float* W4 = (const float*)d_in[5];      // (16,32)
    const float* L0 = (const float*)d_in[6];      // (64,64)
    const float* L1 = (const float*)d_in[7];      // (32,32)
    const float* L2 = (const float*)d_in[8];      // (16,16)
    float* out = (float*)d_out;

    fuse_kernel<<<20, 256>>>(W1, W2, W3, W4, L0, L1, L2);
    knn_part_kernel<<<dim3(NNODES / 256, NB, NCHUNK), 256>>>(coords);
    knn_merge_kernel<<<BN / 8, 256>>>();
    agg_kernel<<<BN / 8, 256>>>(feats, coords, out);
}

// round 6
// speedup vs baseline: 1.7268x; 1.1410x over previous
#include <cuda_runtime.h>
#include <cstddef>

#define NNODES 4096
#define NB 4
#define BN (NNODES * NB)
#define DFEAT 240
#define KNN 8
#define NCHUNK 2
#define CHUNK (NNODES / NCHUNK)   // 2048 candidates per chunk

// Scratch (allocation-free rule: __device__ globals)
__device__ int   g_knn[BN * KNN];
__device__ float g_pd[BN * NCHUNK * KNN];
__device__ int   g_pi[BN * NCHUNK * KNN];
// Fused (W @ L) matrices, output scales baked in
__device__ float g_WL0[32 * 64];   // (W2@L0)  * c2/8
__device__ float g_WL1a[64 * 32];  // (W1@L1)  * c1/sqrt(32)
__device__ float g_WL1b[16 * 32];  // (W4@L1)  * c4/sqrt(32)
__device__ float g_WL2[32 * 16];   // (W3@L2)  * c3/4

// T[a][k] = (Cm[a] . ev)[k], Cm = real Wigner 1x1->2 coupling / sqrt(5)
__device__ __forceinline__ void compute_T(float ex, float ey, float ez, float T[5][3]) {
    const float sc = 0.31622776601683794f;   // 1/sqrt(2)/sqrt(5)
    const float tc = 0.18257418583505536f;   // 1/sqrt(6)/sqrt(5)
    T[0][0] = sc * ey;  T[0][1] = sc * ex;   T[0][2] = 0.f;
    T[1][0] = sc * ez;  T[1][1] = 0.f;       T[1][2] = sc * ex;
    T[2][0] = 0.f;      T[2][1] = sc * ez;   T[2][2] = sc * ey;
    T[3][0] = sc * ex;  T[3][1] = -sc * ey;  T[3][2] = 0.f;
    T[4][0] = -tc * ex; T[4][1] = -tc * ey;  T[4][2] = 2.f * tc * ez;
}

// Branchless sorted insert (ascending; bd[7] = worst). Compare-exchange sweep:
// keeps array sorted, ejects the largest. Ties: earlier-inserted (= smaller
// candidate index, since we scan in index order) stays closer to the front.
__device__ __forceinline__ void bubble_insert(float bd[8], int bi[8], float s, int gj) {
    float cur = s; int curi = gj;
#pragma unroll
    for (int p = 0; p < 8; p++) {
        bool pred = cur < bd[p];
        float lo = fminf(bd[p], cur);
        float hi = fmaxf(bd[p], cur);
        bd[p] = lo; cur = hi;
        int ti = bi[p];
        bi[p] = pred ? curi : bi[p];
        curi  = pred ? ti   : curi;
    }
}

// ============================================================================
// Kernel 1a: partial kNN. Thread = (query, half). Scans 2048 candidates from
// a float4 (x,y,z,|c|^2/2) shared tile; rank by s = h - q.c (monotone in d^2).
// Per-candidate branch -> branchless bubble insert (collective-P ~38%).
// ============================================================================
__global__ __launch_bounds__(128) void knn_part_kernel(const float* __restrict__ coords) {
    __shared__ float4 tile[CHUNK];                // 32KB
    int b = blockIdx.y, chunk = blockIdx.z;
    int cbase = chunk * CHUNK;
    const float* cb = coords + (size_t)b * NNODES * 3;

    for (int k = threadIdx.x; k < CHUNK; k += 128) {
        float x = cb[(cbase + k) * 3];
        float y = cb[(cbase + k) * 3 + 1];
        float z = cb[(cbase + k) * 3 + 2];
        tile[k] = make_float4(x, y, z, 0.5f * fmaf(x, x, fmaf(y, y, z * z)));
    }
    __syncthreads();

    int q = (blockIdx.x << 7) + threadIdx.x;
    float qx = cb[3 * q], qy = cb[3 * q + 1], qz = cb[3 * q + 2];
    float nqx = -qx, nqy = -qy, nqz = -qz;

    float bd[8];
    int   bi[8];
#pragma unroll
    for (int p = 0; p < 8; p++) { bd[p] = 3.9e38f; bi[p] = 0x7fffffff; }

    for (int g = 0; g < CHUNK; g += 4) {
        float4 c0 = tile[g],     c1 = tile[g + 1];
        float4 c2 = tile[g + 2], c3 = tile[g + 3];
        float s0 = fmaf(nqx, c0.x, fmaf(nqy, c0.y, fmaf(nqz, c0.z, c0.w)));
        float s1 = fmaf(nqx, c1.x, fmaf(nqy, c1.y, fmaf(nqz, c1.z, c1.w)));
        float s2 = fmaf(nqx, c2.x, fmaf(nqy, c2.y, fmaf(nqz, c2.z, c2.w)));
        float s3 = fmaf(nqx, c3.x, fmaf(nqy, c3.y, fmaf(nqz, c3.z, c3.w)));
        int j0 = cbase + g;
        if (s0 < bd[7] && j0     != q) bubble_insert(bd, bi, s0, j0);
        if (s1 < bd[7] && j0 + 1 != q) bubble_insert(bd, bi, s1, j0 + 1);
        if (s2 < bd[7] && j0 + 2 != q) bubble_insert(bd, bi, s2, j0 + 2);
        if (s3 < bd[7] && j0 + 3 != q) bubble_insert(bd, bi, s3, j0 + 3);
    }

    int qflat = b * NNODES + q;
    int obase = (qflat * NCHUNK + chunk) * KNN;
#pragma unroll
    for (int r = 0; r < KNN; r++) {
        g_pd[obase + r] = bd[r];
        g_pi[obase + r] = b * NNODES + bi[r];     // flat sender id
    }
}

// ============================================================================
// Kernel 1b: merge. Warp per query: 16 partials in lanes 0-15, 8 rounds of
// lexicographic (val, idx) butterfly argmin; winner masked out by unique id.
// ============================================================================
__global__ __launch_bounds__(256) void knn_merge_kernel() {
    int warp = threadIdx.x >> 5, lane = threadIdx.x & 31;
    int qf = blockIdx.x * 8 + warp;
    int base = qf * NCHUNK * KNN;                 // 16 contiguous entries

    float v = (lane < 16) ? g_pd[base + lane] : 3.95e38f;
    int  id = (lane < 16) ? g_pi[base + lane] : 0x7fffffff;

#pragma unroll
    for (int r = 0; r < KNN; r++) {
        float mv = v; int mi = id;
#pragma unroll
        for (int off = 16; off >= 1; off >>= 1) {
            float ov = __shfl_xor_sync(0xffffffffu, mv, off);
            int   oi = __shfl_xor_sync(0xffffffffu, mi, off);
            if (ov < mv || (ov == mv && oi < mi)) { mv = ov; mi = oi; }
        }
        if (lane == r) g_knn[qf * KNN + r] = mi;  // spread stores
        if (id == mi) v = 3.95e38f;               // node ids unique across chunks
    }
}

// ============================================================================
// Kernel 2: fuse W and L matrices (W commutes with aggregation) + bake scales.
// ============================================================================
__global__ __launch_bounds__(256) void fuse_kernel(
    const float* __restrict__ W1, const float* __restrict__ W2,
    const float* __restrict__ W3, const float* __restrict__ W4,
    const float* __restrict__ L0, const float* __restrict__ L1,
    const float* __restrict__ L2) {
    const float c1 = 0.11180339887498949f;   // sqrt(1/80)
    const float c2 = 0.10206207261596575f;   // sqrt(1/96)
    const float c3 = 0.39528470752104744f;   // sqrt(5/32)
    const float c4 = 0.19364916731037085f;   // sqrt(3/80)
    const float is32 = 0.17677669529663687f; // 1/sqrt(32)
    int idx = blockIdx.x * 256 + threadIdx.x;
    if (idx < 2048) {                         // WL0 = W2@L0 : (32,64)
        int u = idx >> 6, w2 = idx & 63;
        float acc = 0.f;
        for (int w = 0; w < 64; w++) acc = fmaf(W2[u * 64 + w], L0[w * 64 + w2], acc);
        g_WL0[idx] = (c2 * 0.125f) * acc;
    } else if (idx < 4096) {                  // WL1a = W1@L1 : (64,32)
        int t = idx - 2048, u = t >> 5, w2 = t & 31;
        float acc = 0.f;
        for (int w = 0; w < 32; w++) acc = fmaf(W1[u * 32 + w], L1[w * 32 + w2], acc);
        g_WL1a[t] = (c1 * is32) * acc;
    } else if (idx < 4608) {                  // WL1b = W4@L1 : (16,32)
        int t = idx - 4096, u = t >> 5, w2 = t & 31;
        float acc = 0.f;
        for (int w = 0; w < 32; w++) acc = fmaf(W4[u * 32 + w], L1[w * 32 + w2], acc);
        g_WL1b[t] = (c4 * is32) * acc;
    } else {                                  // WL2 = W3@L2 : (32,16)
        int t = idx - 4608, u = t >> 4, w2 = t & 15;
        float acc = 0.f;
        for (int w = 0; w < 16; w++) acc = fmaf(W3[u * 16 + w], L2[w * 16 + w2], acc);
        g_WL2[t] = (c3 * 0.25f) * acc;
    }
}

// ============================================================================
// Kernel 3: fused aggregation. Warp per node. Direct LDG of exactly the
// feature elements each lane needs; neighbor ids + coords front-batched.
// Then fused WL linears from shared.
// ============================================================================
__global__ __launch_bounds__(256) void agg_kernel(
    const float* __restrict__ feats, const float* __restrict__ coords,
    float* __restrict__ out) {
    __shared__ float sWL0[2048], sWL1a[2048], sWL1b[512], sWL2[512];
    __shared__ float sag[8][440];
    for (int k = threadIdx.x; k < 2048; k += 256) { sWL0[k] = g_WL0[k]; sWL1a[k] = g_WL1a[k]; }
    for (int k = threadIdx.x; k < 512;  k += 256) { sWL1b[k] = g_WL1b[k]; sWL2[k] = g_WL2[k]; }

    int warp = threadIdx.x >> 5, lane = threadIdx.x & 31;
    int node = (blockIdx.x << 3) + warp;
    float qx = coords[node * 3], qy = coords[node * 3 + 1], qz = coords[node * 3 + 2];

    // front-batch neighbor ids (32B aligned) and edge vectors
    int4 n0 = *(const int4*)(g_knn + node * KNN);
    int4 n1 = *(const int4*)(g_knn + node * KNN + 4);
    int nbr[8] = {n0.x, n0.y, n0.z, n0.w, n1.x, n1.y, n1.z, n1.w};
    float ex[8], ey[8], ez[8];
#pragma unroll
    for (int r = 0; r < 8; r++) {
        ex[r] = coords[nbr[r] * 3]     - qx;
        ey[r] = coords[nbr[r] * 3 + 1] - qy;
        ez[r] = coords[nbr[r] * 3 + 2] - qz;
    }

    float a0 = 0.f;
    float a1a0[3] = {0.f, 0.f, 0.f};
    float a1a1[3] = {0.f, 0.f, 0.f};
    float a1b[3]  = {0.f, 0.f, 0.f};
    float a2[5]   = {0.f, 0.f, 0.f, 0.f, 0.f};

#pragma unroll
    for (int r = 0; r < KNN; r++) {
        const float* f = feats + (size_t)nbr[r] * DFEAT;
        float f0a = f[lane];                       // coalesced
        float f0b = f[32 + lane];                  // coalesced
        float x1v[3];
#pragma unroll
        for (int i = 0; i < 3; i++) x1v[i] = f[64 + 3 * lane + i];
        float x2v[5];
        if (lane < 16) {
#pragma unroll
            for (int a = 0; a < 5; a++) x2v[a] = f[160 + 5 * lane + a];
        }

        float T[5][3];
        compute_T(ex[r], ey[r], ez[r], T);
        float e[3] = {ex[r], ey[r], ez[r]};

#pragma unroll
        for (int k = 0; k < 3; k++) {
            a1a0[k] = fmaf(f0a, e[k], a1a0[k]);
            a1a1[k] = fmaf(f0b, e[k], a1a1[k]);
        }
#pragma unroll
        for (int i = 0; i < 3; i++) a0 = fmaf(x1v[i], e[i], a0);
#pragma unroll
        for (int a = 0; a < 5; a++)
#pragma unroll
            for (int i = 0; i < 3; i++) a2[a] = fmaf(x1v[i], T[a][i], a2[a]);
        if (lane < 16) {
#pragma unroll
            for (int a = 0; a < 5; a++)
#pragma unroll
                for (int k = 0; k < 3; k++) a1b[k] = fmaf(x2v[a], T[a][k], a1b[k]);
        }
    }

    __syncthreads();   // sWL ready

    // stage aggregates: [0,32) a0 | 32+3u+k (u<64) a1a | 224+3u+k (u<16) a1b | 272+5u+a a2
    float* ag = sag[warp];
    ag[lane] = a0;
#pragma unroll
    for (int k = 0; k < 3; k++) {
        ag[32 + 3 * lane + k]        = a1a0[k];
        ag[32 + 3 * (lane + 32) + k] = a1a1[k];
    }
    if (lane < 16) {
#pragma unroll
        for (int k = 0; k < 3; k++) ag[224 + 3 * lane + k] = a1b[k];
    }
#pragma unroll
    for (int a = 0; a < 5; a++) ag[272 + 5 * lane + a] = a2[a];
    __syncwarp();

    float* o = out + (size_t)node * DFEAT;
    {   // y0[w'] = sum_u a0[u] WL0[u,w']   (w' = 2lane, 2lane+1)
        float y0 = 0.f, y1v = 0.f;
#pragma unroll
        for (int u = 0; u < 32; u++) {
            float av = ag[u];
            y0  = fmaf(av, sWL0[u * 64 + 2 * lane],     y0);
            y1v = fmaf(av, sWL0[u * 64 + 2 * lane + 1], y1v);
        }
        o[2 * lane]     = y0;
        o[2 * lane + 1] = y1v;
    }
    {   // y1[w',k] = sum_{u<64} a1a[u,k] WL1a[u,w'] + sum_{u<16} a1b[u,k] WL1b[u,w']
        float y[3] = {0.f, 0.f, 0.f};
#pragma unroll
        for (int u = 0; u < 64; u++) {
            float lw = sWL1a[u * 32 + lane];
#pragma unroll
            for (int k = 0; k < 3; k++) y[k] = fmaf(ag[32 + 3 * u + k], lw, y[k]);
        }
#pragma unroll
        for (int u = 0; u < 16; u++) {
            float lw = sWL1b[u * 32 + lane];
#pragma unroll
            for (int k = 0; k < 3; k++) y[k] = fmaf(ag[224 + 3 * u + k], lw, y[k]);
        }
#pragma unroll
        for (int k = 0; k < 3; k++) o[64 + 3 * lane + k] = y[k];
    }
    if (lane < 16) {   // y2[w',a] = sum_u a2[u,a] WL2[u,w']
        float y[5] = {0.f, 0.f, 0.f, 0.f, 0.f};
#pragma unroll
        for (int u = 0; u < 32; u++) {
            float lw = sWL2[u * 16 + lane];
#pragma unroll
            for (int a = 0; a < 5; a++) y[a] = fmaf(ag[272 + 5 * u + a], lw, y[a]);
        }
#pragma unroll
        for (int a = 0; a < 5; a++) o[160 + 5 * lane + a] = y[a];
    }
}

// ============================================================================
extern "C" void kernel_launch(void* const* d_in, const int* in_sizes, int n_in,
                              void* d_out, int out_size) {
    const float* feats  = (const float*)d_in[0];  // (4,4096,240)
    const float* coords = (const float*)d_in[1];  // (4,4096,3)
    const float* W1 = (const float*)d_in[2];      // (64,32)
    const float* W2 = (const float*)d_in[3];      // (32,64)
    const float* W3 = (const float*)d_in[4];      // (32,16)
    const float* W4 = (const float*)d_in[5];      // (16,32)
    const float* L0 = (const float*)d_in[6];      // (64,64)
    const float* L1 = (const float*)d_in[7];      // (32,32)
    const float* L2 = (const float*)d_in[8];      // (16,16)
    float* out = (float*)d_out;

    fuse_kernel<<<20, 256>>>(W1, W2, W3, W4, L0, L1, L2);
    knn_part_kernel<<<dim3(NNODES / 128, NB, NCHUNK), 128>>>(coords);
    knn_merge_kernel<<<BN / 8, 256>>>();
    agg_kernel<<<BN / 8, 256>>>(feats, coords, out);
}